// round 2
// baseline (speedup 1.0000x reference)
#include <cuda_runtime.h>
#include <cuda_fp16.h>
#include <cstdint>

// Problem constants (fixed shapes for this problem instance)
#define T_TOK 4096      // B*S
#define D_DIM 1024
#define E_NUM 8
#define F_DIM 4096
#define NSLOT (T_TOK * 2)   // top_k = 2

// ---------------- static scratch (no cudaMalloc allowed) ----------------
__device__ __half g_xg[(size_t)NSLOT * D_DIM];      // gathered tokens, fp16 (16 MB)
__device__ __half g_h[(size_t)NSLOT * F_DIM];       // hidden activations, fp16 (64 MB)
__device__ int    g_tok_e[NSLOT];                   // per token: 2 expert ids
__device__ float  g_tok_g[NSLOT];                   // per token: 2 gates
__device__ int    g_counts[E_NUM];
__device__ int    g_offsets[E_NUM];
__device__ int    g_cursor[E_NUM];
__device__ int    g_token_of_slot[NSLOT];
__device__ float  g_gate_of_slot[NSLOT];

__device__ __forceinline__ float siluf(float v) {
    return v / (1.f + __expf(-v));
}

// ---------------- kernel 1: zero output + counters ----------------
__global__ void k_zero(float* __restrict__ out) {
    int i = blockIdx.x * blockDim.x + threadIdx.x;
    if (i < T_TOK * D_DIM) out[i] = 0.f;
    if (i < E_NUM) g_counts[i] = 0;
}

// ---------------- kernel 2: router (warp per token, fp32) ----------------
__global__ void k_router(const float* __restrict__ x,
                         const float* __restrict__ Wr,
                         const float* __restrict__ br) {
    int warp = threadIdx.x >> 5, lane = threadIdx.x & 31;
    int t = blockIdx.x * 8 + warp;
    if (t >= T_TOK) return;

    const float4* xr = (const float4*)(x + (size_t)t * D_DIM);
    float acc[E_NUM];
#pragma unroll
    for (int e = 0; e < E_NUM; e++) acc[e] = 0.f;

    for (int i = lane; i < D_DIM / 4; i += 32) {
        float4 xv = xr[i];
#pragma unroll
        for (int e = 0; e < E_NUM; e++) {
            float4 wv = ((const float4*)(Wr + (size_t)e * D_DIM))[i];
            acc[e] += xv.x * wv.x + xv.y * wv.y + xv.z * wv.z + xv.w * wv.w;
        }
    }
#pragma unroll
    for (int e = 0; e < E_NUM; e++) {
#pragma unroll
        for (int off = 16; off > 0; off >>= 1)
            acc[e] += __shfl_down_sync(0xffffffffu, acc[e], off);
    }
    if (lane == 0) {
        float l[E_NUM];
#pragma unroll
        for (int e = 0; e < E_NUM; e++) l[e] = acc[e] + br[e];
        // top-2, lowest-index tie-break (matches jax.lax.top_k)
        int i1 = 0;
#pragma unroll
        for (int e = 1; e < E_NUM; e++) if (l[e] > l[i1]) i1 = e;
        int i2 = (i1 == 0) ? 1 : 0;
#pragma unroll
        for (int e = 0; e < E_NUM; e++)
            if (e != i1 && l[e] > l[i2]) i2 = e;
        float d  = l[i2] - l[i1];        // <= 0
        float e2 = __expf(d);
        float inv = 1.f / (1.f + e2);
        g_tok_e[2 * t]     = i1; g_tok_g[2 * t]     = inv;
        g_tok_e[2 * t + 1] = i2; g_tok_g[2 * t + 1] = e2 * inv;
        atomicAdd(&g_counts[i1], 1);
        atomicAdd(&g_counts[i2], 1);
    }
}

// ---------------- kernel 3: expert offsets (tiny) ----------------
__global__ void k_offsets() {
    if (threadIdx.x == 0 && blockIdx.x == 0) {
        int off = 0;
        for (int e = 0; e < E_NUM; e++) {
            g_offsets[e] = off;
            g_cursor[e]  = off;
            off += g_counts[e];
        }
    }
}

// ---------------- kernel 4: assign slots ----------------
__global__ void k_assign() {
    int t = blockIdx.x * blockDim.x + threadIdx.x;
    if (t >= T_TOK) return;
#pragma unroll
    for (int j = 0; j < 2; j++) {
        int e = g_tok_e[2 * t + j];
        int s = atomicAdd(&g_cursor[e], 1);
        g_token_of_slot[s] = t;
        g_gate_of_slot[s]  = g_tok_g[2 * t + j];
    }
}

// ---------------- kernel 5: gather x rows -> fp16 compact buffer ----------------
__global__ void k_gather(const float* __restrict__ x) {
    int s = blockIdx.x;
    int tok = g_token_of_slot[s];
    const float4* src = (const float4*)(x + (size_t)tok * D_DIM);
    uint2* dst = (uint2*)(g_xg + (size_t)s * D_DIM);
    for (int i = threadIdx.x; i < D_DIM / 4; i += blockDim.x) {
        float4 v = src[i];
        __half2 lo = __floats2half2_rn(v.x, v.y);
        __half2 hi = __floats2half2_rn(v.z, v.w);
        uint2 u;
        u.x = *(uint32_t*)&lo;
        u.y = *(uint32_t*)&hi;
        dst[i] = u;
    }
}

// ---------------- GEMM common ----------------
#define BM 128
#define BN 64
#define BK 32
#define SA 40   // padded smem row stride in halves (conflict-free for frag loads)

__device__ __forceinline__ void mma16816(float c[4],
                                         const uint32_t a[4],
                                         const uint32_t b[2]) {
    asm volatile(
        "mma.sync.aligned.m16n8k16.row.col.f32.f16.f16.f32 "
        "{%0,%1,%2,%3}, {%4,%5,%6,%7}, {%8,%9}, {%0,%1,%2,%3};\n"
        : "+f"(c[0]), "+f"(c[1]), "+f"(c[2]), "+f"(c[3])
        : "r"(a[0]), "r"(a[1]), "r"(a[2]), "r"(a[3]), "r"(b[0]), "r"(b[1]));
}

// ---------------- kernel 6: GEMM1  h = silu(xg @ W1[e]^T + b1[e]) ----------------
// A: g_xg (fp16, lda=D_DIM), B: W1[e] row-major [F,D] fp32 (converted in-flight)
__global__ __launch_bounds__(256) void k_gemm1(const float* __restrict__ W1,
                                               const float* __restrict__ b1) {
    int e   = blockIdx.z;
    int len = g_counts[e];
    int m0  = blockIdx.y * BM;
    if (m0 >= len) return;
    int n0  = blockIdx.x * BN;
    int off = g_offsets[e];

    __shared__ __half As[BM][SA];
    __shared__ __half Bs[BN][SA];

    const __half* A = g_xg + (size_t)off * D_DIM;
    const float*  B = W1 + (size_t)e * F_DIM * D_DIM;

    int tid = threadIdx.x;
    int warp = tid >> 5, lane = tid & 31;
    int wm = warp >> 1, wn = warp & 1;      // 4 x 2 warp grid
    int mbase = wm * 32, nbase = wn * 32;
    int grp = lane >> 2, q = lane & 3;

    float acc[2][4][4];
#pragma unroll
    for (int mt = 0; mt < 2; mt++)
#pragma unroll
        for (int nt = 0; nt < 4; nt++)
#pragma unroll
            for (int i = 0; i < 4; i++) acc[mt][nt][i] = 0.f;

    for (int k0 = 0; k0 < D_DIM; k0 += BK) {
        // A tile: 128 rows x 32 halves (guarded gather rows are already compact)
#pragma unroll
        for (int it = 0; it < 2; it++) {
            int i = tid + it * 256;
            int r = i >> 2, cs = i & 3;
            int gr = m0 + r;
            uint4 v = make_uint4(0, 0, 0, 0);
            if (gr < len)
                v = *(const uint4*)(A + (size_t)gr * D_DIM + k0 + cs * 8);
            *(uint4*)&As[r][cs * 8] = v;
        }
        // B tile: 64 rows x 32 floats -> fp16
#pragma unroll
        for (int it = 0; it < 2; it++) {
            int i = tid + it * 256;
            int r = i >> 3, cs = i & 7;
            float4 v = *(const float4*)(B + (size_t)(n0 + r) * D_DIM + k0 + cs * 4);
            __half2 lo = __floats2half2_rn(v.x, v.y);
            __half2 hi = __floats2half2_rn(v.z, v.w);
            uint2 u;
            u.x = *(uint32_t*)&lo;
            u.y = *(uint32_t*)&hi;
            *(uint2*)&Bs[r][cs * 4] = u;
        }
        __syncthreads();

#pragma unroll
        for (int kk = 0; kk < BK; kk += 16) {
            uint32_t a[2][4], b[4][2];
#pragma unroll
            for (int mt = 0; mt < 2; mt++) {
                const __half* p = &As[mbase + mt * 16 + grp][kk + q * 2];
                a[mt][0] = *(const uint32_t*)p;
                a[mt][1] = *(const uint32_t*)(p + 8 * SA);
                a[mt][2] = *(const uint32_t*)(p + 8);
                a[mt][3] = *(const uint32_t*)(p + 8 * SA + 8);
            }
#pragma unroll
            for (int nt = 0; nt < 4; nt++) {
                const __half* p = &Bs[nbase + nt * 8 + grp][kk + q * 2];
                b[nt][0] = *(const uint32_t*)p;
                b[nt][1] = *(const uint32_t*)(p + 8);
            }
#pragma unroll
            for (int mt = 0; mt < 2; mt++)
#pragma unroll
                for (int nt = 0; nt < 4; nt++)
                    mma16816(acc[mt][nt], a[mt], b[nt]);
        }
        __syncthreads();
    }

    // epilogue: bias + silu -> fp16 h
    const float* b1e = b1 + (size_t)e * F_DIM + n0;
#pragma unroll
    for (int mt = 0; mt < 2; mt++) {
        int r0 = m0 + mbase + mt * 16 + grp;
#pragma unroll
        for (int nt = 0; nt < 4; nt++) {
            int c = nbase + nt * 8 + q * 2;
            float bv0 = b1e[c], bv1 = b1e[c + 1];
            if (r0 < len) {
                __half2 h2 = __floats2half2_rn(siluf(acc[mt][nt][0] + bv0),
                                               siluf(acc[mt][nt][1] + bv1));
                *(uint32_t*)(g_h + (size_t)(off + r0) * F_DIM + n0 + c) =
                    *(uint32_t*)&h2;
            }
            if (r0 + 8 < len) {
                __half2 h2 = __floats2half2_rn(siluf(acc[mt][nt][2] + bv0),
                                               siluf(acc[mt][nt][3] + bv1));
                *(uint32_t*)(g_h + (size_t)(off + r0 + 8) * F_DIM + n0 + c) =
                    *(uint32_t*)&h2;
            }
        }
    }
}

// ---------------- kernel 7: GEMM2  y += gate * (h @ W2[e]^T + b2[e]) ----------------
// A: g_h (fp16, lda=F_DIM), B: W2[e] row-major [D,F] fp32
__global__ __launch_bounds__(256) void k_gemm2(const float* __restrict__ W2,
                                               const float* __restrict__ b2,
                                               float* __restrict__ out) {
    int e   = blockIdx.z;
    int len = g_counts[e];
    int m0  = blockIdx.y * BM;
    if (m0 >= len) return;
    int n0  = blockIdx.x * BN;
    int off = g_offsets[e];

    __shared__ __half As[BM][SA];
    __shared__ __half Bs[BN][SA];

    const __half* A = g_h + (size_t)off * F_DIM;
    const float*  B = W2 + (size_t)e * D_DIM * F_DIM;

    int tid = threadIdx.x;
    int warp = tid >> 5, lane = tid & 31;
    int wm = warp >> 1, wn = warp & 1;
    int mbase = wm * 32, nbase = wn * 32;
    int grp = lane >> 2, q = lane & 3;

    float acc[2][4][4];
#pragma unroll
    for (int mt = 0; mt < 2; mt++)
#pragma unroll
        for (int nt = 0; nt < 4; nt++)
#pragma unroll
            for (int i = 0; i < 4; i++) acc[mt][nt][i] = 0.f;

    for (int k0 = 0; k0 < F_DIM; k0 += BK) {
#pragma unroll
        for (int it = 0; it < 2; it++) {
            int i = tid + it * 256;
            int r = i >> 2, cs = i & 3;
            int gr = m0 + r;
            uint4 v = make_uint4(0, 0, 0, 0);
            if (gr < len)
                v = *(const uint4*)(A + (size_t)gr * F_DIM + k0 + cs * 8);
            *(uint4*)&As[r][cs * 8] = v;
        }
#pragma unroll
        for (int it = 0; it < 2; it++) {
            int i = tid + it * 256;
            int r = i >> 3, cs = i & 7;
            float4 v = *(const float4*)(B + (size_t)(n0 + r) * F_DIM + k0 + cs * 4);
            __half2 lo = __floats2half2_rn(v.x, v.y);
            __half2 hi = __floats2half2_rn(v.z, v.w);
            uint2 u;
            u.x = *(uint32_t*)&lo;
            u.y = *(uint32_t*)&hi;
            *(uint2*)&Bs[r][cs * 4] = u;
        }
        __syncthreads();

#pragma unroll
        for (int kk = 0; kk < BK; kk += 16) {
            uint32_t a[2][4], b[4][2];
#pragma unroll
            for (int mt = 0; mt < 2; mt++) {
                const __half* p = &As[mbase + mt * 16 + grp][kk + q * 2];
                a[mt][0] = *(const uint32_t*)p;
                a[mt][1] = *(const uint32_t*)(p + 8 * SA);
                a[mt][2] = *(const uint32_t*)(p + 8);
                a[mt][3] = *(const uint32_t*)(p + 8 * SA + 8);
            }
#pragma unroll
            for (int nt = 0; nt < 4; nt++) {
                const __half* p = &Bs[nbase + nt * 8 + grp][kk + q * 2];
                b[nt][0] = *(const uint32_t*)p;
                b[nt][1] = *(const uint32_t*)(p + 8);
            }
#pragma unroll
            for (int mt = 0; mt < 2; mt++)
#pragma unroll
                for (int nt = 0; nt < 4; nt++)
                    mma16816(acc[mt][nt], a[mt], b[nt]);
        }
        __syncthreads();
    }

    // epilogue: bias, gate-scale, scatter-add into y
    const float* b2e = b2 + (size_t)e * D_DIM + n0;
#pragma unroll
    for (int mt = 0; mt < 2; mt++) {
        int r0 = m0 + mbase + mt * 16 + grp;
        int rows[2] = {r0, r0 + 8};
#pragma unroll
        for (int rr = 0; rr < 2; rr++) {
            int r = rows[rr];
            if (r >= len) continue;
            int slot = off + r;
            int tok  = g_token_of_slot[slot];
            float g  = g_gate_of_slot[slot];
            float* yrow = out + (size_t)tok * D_DIM + n0;
#pragma unroll
            for (int nt = 0; nt < 4; nt++) {
                int c = nbase + nt * 8 + q * 2;
                float v0 = g * (acc[mt][nt][rr * 2 + 0] + b2e[c]);
                float v1 = g * (acc[mt][nt][rr * 2 + 1] + b2e[c + 1]);
                atomicAdd(&yrow[c], v0);
                atomicAdd(&yrow[c + 1], v1);
            }
        }
    }
}

// ---------------- launch ----------------
extern "C" void kernel_launch(void* const* d_in, const int* in_sizes, int n_in,
                              void* d_out, int out_size) {
    const float* x  = (const float*)d_in[0];
    const float* Wr = (const float*)d_in[1];
    const float* br = (const float*)d_in[2];
    const float* W1 = (const float*)d_in[3];
    const float* b1 = (const float*)d_in[4];
    const float* W2 = (const float*)d_in[5];
    const float* b2 = (const float*)d_in[6];
    float* out = (float*)d_out;

    k_zero<<<(T_TOK * D_DIM + 255) / 256, 256>>>(out);
    k_router<<<T_TOK / 8, 256>>>(x, Wr, br);
    k_offsets<<<1, 32>>>();
    k_assign<<<(T_TOK + 255) / 256, 256>>>();
    k_gather<<<NSLOT, 128>>>(x);
    k_gemm1<<<dim3(F_DIM / BN, (T_TOK + BM - 1) / BM, E_NUM), 256>>>(W1, b1);
    k_gemm2<<<dim3(D_DIM / BN, (T_TOK + BM - 1) / BM, E_NUM), 256>>>(W2, b2, out);
}

// round 3
// speedup vs baseline: 1.1459x; 1.1459x over previous
#include <cuda_runtime.h>
#include <cuda_fp16.h>
#include <cstdint>

// Problem constants
#define T_TOK 4096      // B*S
#define D_DIM 1024
#define E_NUM 8
#define F_DIM 4096
#define NSLOT (T_TOK * 2)   // top_k = 2
#define PAD_ROWS 256        // allow unguarded BM-tile over-read

// GEMM config
#define BM 256
#define BN 128
#define BK 32
#define SA 40               // padded smem row stride (halves); 80B, 16B-aligned
#define NTHR 512
#define A_STAGE (BM * SA)
#define B_STAGE (BN * SA)
#define SMEM_BYTES ((2 * A_STAGE + 2 * B_STAGE) * 2)

// ---------------- static scratch ----------------
__device__ __half g_xg[(size_t)(NSLOT + PAD_ROWS) * D_DIM];
__device__ __half g_h[(size_t)(NSLOT + PAD_ROWS) * F_DIM];
__device__ __half g_w1h[(size_t)E_NUM * F_DIM * D_DIM];   // 67 MB fp16
__device__ __half g_w2h[(size_t)E_NUM * D_DIM * F_DIM];   // 67 MB fp16
__device__ int    g_tok_e[NSLOT];
__device__ float  g_tok_g[NSLOT];
__device__ int    g_counts[E_NUM];
__device__ int    g_offsets[E_NUM];
__device__ int    g_cursor[E_NUM];
__device__ int    g_token_of_slot[NSLOT];
__device__ float  g_gate_of_slot[NSLOT];

__device__ __forceinline__ float siluf(float v) {
    return v / (1.f + __expf(-v));
}

// ---------------- cp.async helpers ----------------
__device__ __forceinline__ void cp16(uint32_t dst, const void* src) {
    asm volatile("cp.async.cg.shared.global [%0], [%1], 16;\n"
                 :: "r"(dst), "l"(src));
}
__device__ __forceinline__ void cp_commit() {
    asm volatile("cp.async.commit_group;\n");
}
template <int N>
__device__ __forceinline__ void cp_wait() {
    asm volatile("cp.async.wait_group %0;\n" :: "n"(N));
}

__device__ __forceinline__ void mma16816(float c[4],
                                         const uint32_t a[4],
                                         const uint32_t b[2]) {
    asm volatile(
        "mma.sync.aligned.m16n8k16.row.col.f32.f16.f16.f32 "
        "{%0,%1,%2,%3}, {%4,%5,%6,%7}, {%8,%9}, {%0,%1,%2,%3};\n"
        : "+f"(c[0]), "+f"(c[1]), "+f"(c[2]), "+f"(c[3])
        : "r"(a[0]), "r"(a[1]), "r"(a[2]), "r"(a[3]), "r"(b[0]), "r"(b[1]));
}

// ---------------- kernel: zero output + counters ----------------
__global__ void k_zero(float* __restrict__ out) {
    int i = blockIdx.x * blockDim.x + threadIdx.x;
    if (i < T_TOK * D_DIM) out[i] = 0.f;
    if (i < E_NUM) g_counts[i] = 0;
}

// ---------------- kernel: weight fp32 -> fp16 ----------------
__global__ void k_convert(const float* __restrict__ W1,
                          const float* __restrict__ W2) {
    size_t n4 = (size_t)E_NUM * F_DIM * D_DIM / 4;
    for (size_t i = (size_t)blockIdx.x * blockDim.x + threadIdx.x; i < n4;
         i += (size_t)gridDim.x * blockDim.x) {
        float4 v = ((const float4*)W1)[i];
        __half2 lo = __floats2half2_rn(v.x, v.y);
        __half2 hi = __floats2half2_rn(v.z, v.w);
        uint2 u;
        u.x = *(uint32_t*)&lo; u.y = *(uint32_t*)&hi;
        ((uint2*)g_w1h)[i] = u;
        v = ((const float4*)W2)[i];
        lo = __floats2half2_rn(v.x, v.y);
        hi = __floats2half2_rn(v.z, v.w);
        u.x = *(uint32_t*)&lo; u.y = *(uint32_t*)&hi;
        ((uint2*)g_w2h)[i] = u;
    }
}

// ---------------- kernel: router ----------------
__global__ void k_router(const float* __restrict__ x,
                         const float* __restrict__ Wr,
                         const float* __restrict__ br) {
    int warp = threadIdx.x >> 5, lane = threadIdx.x & 31;
    int t = blockIdx.x * 8 + warp;
    if (t >= T_TOK) return;

    const float4* xr = (const float4*)(x + (size_t)t * D_DIM);
    float acc[E_NUM];
#pragma unroll
    for (int e = 0; e < E_NUM; e++) acc[e] = 0.f;

    for (int i = lane; i < D_DIM / 4; i += 32) {
        float4 xv = xr[i];
#pragma unroll
        for (int e = 0; e < E_NUM; e++) {
            float4 wv = ((const float4*)(Wr + (size_t)e * D_DIM))[i];
            acc[e] += xv.x * wv.x + xv.y * wv.y + xv.z * wv.z + xv.w * wv.w;
        }
    }
#pragma unroll
    for (int e = 0; e < E_NUM; e++) {
#pragma unroll
        for (int off = 16; off > 0; off >>= 1)
            acc[e] += __shfl_down_sync(0xffffffffu, acc[e], off);
    }
    if (lane == 0) {
        float l[E_NUM];
#pragma unroll
        for (int e = 0; e < E_NUM; e++) l[e] = acc[e] + br[e];
        int i1 = 0;
#pragma unroll
        for (int e = 1; e < E_NUM; e++) if (l[e] > l[i1]) i1 = e;
        int i2 = (i1 == 0) ? 1 : 0;
#pragma unroll
        for (int e = 0; e < E_NUM; e++)
            if (e != i1 && l[e] > l[i2]) i2 = e;
        float d  = l[i2] - l[i1];
        float e2 = __expf(d);
        float inv = 1.f / (1.f + e2);
        g_tok_e[2 * t]     = i1; g_tok_g[2 * t]     = inv;
        g_tok_e[2 * t + 1] = i2; g_tok_g[2 * t + 1] = e2 * inv;
        atomicAdd(&g_counts[i1], 1);
        atomicAdd(&g_counts[i2], 1);
    }
}

// ---------------- kernel: offsets ----------------
__global__ void k_offsets() {
    if (threadIdx.x == 0 && blockIdx.x == 0) {
        int off = 0;
        for (int e = 0; e < E_NUM; e++) {
            g_offsets[e] = off;
            g_cursor[e]  = off;
            off += g_counts[e];
        }
    }
}

// ---------------- kernel: assign slots ----------------
__global__ void k_assign() {
    int t = blockIdx.x * blockDim.x + threadIdx.x;
    if (t >= T_TOK) return;
#pragma unroll
    for (int j = 0; j < 2; j++) {
        int e = g_tok_e[2 * t + j];
        int s = atomicAdd(&g_cursor[e], 1);
        g_token_of_slot[s] = t;
        g_gate_of_slot[s]  = g_tok_g[2 * t + j];
    }
}

// ---------------- kernel: gather x -> fp16 compact ----------------
__global__ void k_gather(const float* __restrict__ x) {
    int s = blockIdx.x;
    int tok = g_token_of_slot[s];
    const float4* src = (const float4*)(x + (size_t)tok * D_DIM);
    uint2* dst = (uint2*)(g_xg + (size_t)s * D_DIM);
    for (int i = threadIdx.x; i < D_DIM / 4; i += blockDim.x) {
        float4 v = src[i];
        __half2 lo = __floats2half2_rn(v.x, v.y);
        __half2 hi = __floats2half2_rn(v.z, v.w);
        uint2 u;
        u.x = *(uint32_t*)&lo; u.y = *(uint32_t*)&hi;
        dst[i] = u;
    }
}

// ---------------- pipelined GEMM core pieces ----------------
// fill one stage: A tile BM x BK halves, B tile BN x BK halves, lda == ldb == LDK
__device__ __forceinline__ void fill_stage(uint32_t as_b, uint32_t bs_b, int s,
                                           const __half* A, const __half* Bw,
                                           int k0, int ldk, int tid) {
#pragma unroll
    for (int it = 0; it < 2; it++) {
        int i = tid + it * NTHR;
        int r = i >> 2, c = i & 3;
        uint32_t dst = as_b + (uint32_t)(s * A_STAGE + r * SA + c * 8) * 2;
        cp16(dst, A + (size_t)r * ldk + k0 + c * 8);
    }
    {
        int r = tid >> 2, c = tid & 3;
        uint32_t dst = bs_b + (uint32_t)(s * B_STAGE + r * SA + c * 8) * 2;
        cp16(dst, Bw + (size_t)r * ldk + k0 + c * 8);
    }
}

__device__ __forceinline__ void compute_stage(const __half* Asb, const __half* Bsb,
                                              int mbase, int nbase, int grp, int q,
                                              float acc[4][4][4]) {
#pragma unroll
    for (int kk = 0; kk < BK; kk += 16) {
        uint32_t a[4][4], b[4][2];
#pragma unroll
        for (int mt = 0; mt < 4; mt++) {
            const __half* p = Asb + (mbase + mt * 16 + grp) * SA + kk + q * 2;
            a[mt][0] = *(const uint32_t*)p;
            a[mt][1] = *(const uint32_t*)(p + 8 * SA);
            a[mt][2] = *(const uint32_t*)(p + 8);
            a[mt][3] = *(const uint32_t*)(p + 8 * SA + 8);
        }
#pragma unroll
        for (int nt = 0; nt < 4; nt++) {
            const __half* p = Bsb + (nbase + nt * 8 + grp) * SA + kk + q * 2;
            b[nt][0] = *(const uint32_t*)p;
            b[nt][1] = *(const uint32_t*)(p + 8);
        }
#pragma unroll
        for (int mt = 0; mt < 4; mt++)
#pragma unroll
            for (int nt = 0; nt < 4; nt++)
                mma16816(acc[mt][nt], a[mt], b[nt]);
    }
}

// ---------------- GEMM1: h = silu(xg @ W1h^T + b1) ----------------
__global__ __launch_bounds__(NTHR) void k_gemm1(const float* __restrict__ b1) {
    int e   = blockIdx.z;
    int len = g_counts[e];
    int m0  = blockIdx.y * BM;
    if (m0 >= len) return;
    int n0  = blockIdx.x * BN;
    int off = g_offsets[e];

    extern __shared__ __half sm[];
    __half* As = sm;
    __half* Bs = sm + 2 * A_STAGE;
    uint32_t as_b = (uint32_t)__cvta_generic_to_shared(As);
    uint32_t bs_b = (uint32_t)__cvta_generic_to_shared(Bs);

    const __half* A  = g_xg + (size_t)(off + m0) * D_DIM;
    const __half* Bw = g_w1h + (size_t)e * F_DIM * D_DIM + (size_t)n0 * D_DIM;

    int tid = threadIdx.x;
    int warp = tid >> 5, lane = tid & 31;
    int wm = warp >> 2, wn = warp & 3;          // 4x4 warps, warp tile 64x32
    int mbase = wm * 64, nbase = wn * 32;
    int grp = lane >> 2, q = lane & 3;

    float acc[4][4][4];
#pragma unroll
    for (int mt = 0; mt < 4; mt++)
#pragma unroll
        for (int nt = 0; nt < 4; nt++)
#pragma unroll
            for (int i = 0; i < 4; i++) acc[mt][nt][i] = 0.f;

    const int NK = D_DIM / BK;   // 32
    fill_stage(as_b, bs_b, 0, A, Bw, 0, D_DIM, tid);
    cp_commit();
    for (int it = 0; it < NK; it++) {
        if (it + 1 < NK) {
            fill_stage(as_b, bs_b, (it + 1) & 1, A, Bw, (it + 1) * BK, D_DIM, tid);
            cp_commit();
            cp_wait<1>();
        } else {
            cp_wait<0>();
        }
        __syncthreads();
        compute_stage(As + (it & 1) * A_STAGE, Bs + (it & 1) * B_STAGE,
                      mbase, nbase, grp, q, acc);
        __syncthreads();
    }

    const float* b1e = b1 + (size_t)e * F_DIM + n0;
#pragma unroll
    for (int mt = 0; mt < 4; mt++) {
        int r0 = m0 + mbase + mt * 16 + grp;
#pragma unroll
        for (int nt = 0; nt < 4; nt++) {
            int c = nbase + nt * 8 + q * 2;
            float bv0 = b1e[c], bv1 = b1e[c + 1];
            if (r0 < len) {
                __half2 h2 = __floats2half2_rn(siluf(acc[mt][nt][0] + bv0),
                                               siluf(acc[mt][nt][1] + bv1));
                *(uint32_t*)(g_h + (size_t)(off + r0) * F_DIM + n0 + c) =
                    *(uint32_t*)&h2;
            }
            if (r0 + 8 < len) {
                __half2 h2 = __floats2half2_rn(siluf(acc[mt][nt][2] + bv0),
                                               siluf(acc[mt][nt][3] + bv1));
                *(uint32_t*)(g_h + (size_t)(off + r0 + 8) * F_DIM + n0 + c) =
                    *(uint32_t*)&h2;
            }
        }
    }
}

// ---------------- GEMM2: y += gate * (h @ W2h^T + b2) ----------------
__global__ __launch_bounds__(NTHR) void k_gemm2(const float* __restrict__ b2,
                                                float* __restrict__ out) {
    int e   = blockIdx.z;
    int len = g_counts[e];
    int m0  = blockIdx.y * BM;
    if (m0 >= len) return;
    int n0  = blockIdx.x * BN;
    int off = g_offsets[e];

    extern __shared__ __half sm[];
    __half* As = sm;
    __half* Bs = sm + 2 * A_STAGE;
    uint32_t as_b = (uint32_t)__cvta_generic_to_shared(As);
    uint32_t bs_b = (uint32_t)__cvta_generic_to_shared(Bs);

    const __half* A  = g_h + (size_t)(off + m0) * F_DIM;
    const __half* Bw = g_w2h + (size_t)e * D_DIM * F_DIM + (size_t)n0 * F_DIM;

    int tid = threadIdx.x;
    int warp = tid >> 5, lane = tid & 31;
    int wm = warp >> 2, wn = warp & 3;
    int mbase = wm * 64, nbase = wn * 32;
    int grp = lane >> 2, q = lane & 3;

    float acc[4][4][4];
#pragma unroll
    for (int mt = 0; mt < 4; mt++)
#pragma unroll
        for (int nt = 0; nt < 4; nt++)
#pragma unroll
            for (int i = 0; i < 4; i++) acc[mt][nt][i] = 0.f;

    const int NK = F_DIM / BK;   // 128
    fill_stage(as_b, bs_b, 0, A, Bw, 0, F_DIM, tid);
    cp_commit();
    for (int it = 0; it < NK; it++) {
        if (it + 1 < NK) {
            fill_stage(as_b, bs_b, (it + 1) & 1, A, Bw, (it + 1) * BK, F_DIM, tid);
            cp_commit();
            cp_wait<1>();
        } else {
            cp_wait<0>();
        }
        __syncthreads();
        compute_stage(As + (it & 1) * A_STAGE, Bs + (it & 1) * B_STAGE,
                      mbase, nbase, grp, q, acc);
        __syncthreads();
    }

    const float* b2e = b2 + (size_t)e * D_DIM + n0;
#pragma unroll
    for (int mt = 0; mt < 4; mt++) {
        int r0 = m0 + mbase + mt * 16 + grp;
        int rows[2] = {r0, r0 + 8};
#pragma unroll
        for (int rr = 0; rr < 2; rr++) {
            int r = rows[rr];
            if (r >= len) continue;
            int slot = off + r;
            int tok  = g_token_of_slot[slot];
            float g  = g_gate_of_slot[slot];
            float* yrow = out + (size_t)tok * D_DIM + n0;
#pragma unroll
            for (int nt = 0; nt < 4; nt++) {
                int c = nbase + nt * 8 + q * 2;
                atomicAdd(&yrow[c],     g * (acc[mt][nt][rr * 2 + 0] + b2e[c]));
                atomicAdd(&yrow[c + 1], g * (acc[mt][nt][rr * 2 + 1] + b2e[c + 1]));
            }
        }
    }
}

// ---------------- launch ----------------
extern "C" void kernel_launch(void* const* d_in, const int* in_sizes, int n_in,
                              void* d_out, int out_size) {
    const float* x  = (const float*)d_in[0];
    const float* Wr = (const float*)d_in[1];
    const float* br = (const float*)d_in[2];
    const float* W1 = (const float*)d_in[3];
    const float* b1 = (const float*)d_in[4];
    const float* W2 = (const float*)d_in[5];
    const float* b2 = (const float*)d_in[6];
    float* out = (float*)d_out;

    static bool attr_set = false;
    if (!attr_set) {
        cudaFuncSetAttribute(k_gemm1, cudaFuncAttributeMaxDynamicSharedMemorySize,
                             SMEM_BYTES);
        cudaFuncSetAttribute(k_gemm2, cudaFuncAttributeMaxDynamicSharedMemorySize,
                             SMEM_BYTES);
        attr_set = true;
    }

    k_zero<<<(T_TOK * D_DIM + 255) / 256, 256>>>(out);
    k_convert<<<4096, 256>>>(W1, W2);
    k_router<<<T_TOK / 8, 256>>>(x, Wr, br);
    k_offsets<<<1, 32>>>();
    k_assign<<<(T_TOK + 255) / 256, 256>>>();
    k_gather<<<NSLOT, 128>>>(x);
    k_gemm1<<<dim3(F_DIM / BN, (T_TOK + BM - 1) / BM, E_NUM), NTHR, SMEM_BYTES>>>(b1);
    k_gemm2<<<dim3(D_DIM / BN, (T_TOK + BM - 1) / BM, E_NUM), NTHR, SMEM_BYTES>>>(b2, out);
}